// round 1
// baseline (speedup 1.0000x reference)
#include <cuda_runtime.h>
#include <math.h>
#include <stdint.h>

#define B 8
#define C 256
#define HW 4096
#define HEADS 2
#define POINTS 4
#define CIN 512
#define TEMB 1024
#define NSPLIT 8

// ---------------- scratch (static device arrays; no allocation) ----------------
__device__ float g_sp[B * HW * C];            // style_proj, channels-last [b][px][c]
__device__ float g_hv[B * HW * 2 * C];        // head_vals,  channels-last [b][px][head*256+c]
__device__ float g_off_partial[NSPLIT * B * 6 * HW];
__device__ float g_off[B * 4 * HW];           // [b][head*2+d][px]
__device__ float g_attn[B * HEADS * HW];      // [b][head][px]
__device__ float g_alpha[B];
__device__ float g_loss_partial[B * 4];

// ---------------- alpha = sigmoid(silu(temb) @ tgate_w^T + tgate_b) ----------------
__global__ void alpha_kernel(const float* __restrict__ temb,
                             const float* __restrict__ tw,
                             const float* __restrict__ tb) {
    int b = blockIdx.x;
    int t = threadIdx.x;
    float s = 0.f;
    for (int k = t; k < TEMB; k += 256) {
        float x = temb[b * TEMB + k];
        float si = x / (1.f + expf(-x));   // silu
        s += si * tw[k];
    }
    __shared__ float red[256];
    red[t] = s; __syncthreads();
    for (int o = 128; o > 0; o >>= 1) {
        if (t < o) red[t] += red[t + o];
        __syncthreads();
    }
    if (t == 0) {
        float v = red[0] + tb[0];
        g_alpha[b] = 1.f / (1.f + expf(-v));
    }
}

// ---------------- style_proj: g_sp[b][px][o] = sum_i S[b][i][px]*W[o][i] + bias[o] ----------------
// M=4096 (px), N=256 (o), K=256. 128x128 tile, 256 threads, 8x8 microtile.
__global__ void __launch_bounds__(256) style_gemm_kernel(
        const float* __restrict__ S, const float* __restrict__ W,
        const float* __restrict__ bias) {
    int b  = blockIdx.z;
    int m0 = blockIdx.x * 128;   // px
    int n0 = blockIdx.y * 128;   // o
    __shared__ float As[8][128];
    __shared__ float Bs[8][132];
    int t = threadIdx.x;
    int tx = t & 15, ty = t >> 4;
    float acc[8][8];
    #pragma unroll
    for (int r = 0; r < 8; r++)
        #pragma unroll
        for (int c = 0; c < 8; c++) acc[r][c] = 0.f;

    const float* Sb = S + (size_t)b * C * HW;
    for (int k0 = 0; k0 < C; k0 += 8) {
        {   // A tile: [k][m], m contiguous -> direct
            int kk = t >> 5;
            int mm = (t & 31) * 4;
            float4 v = *(const float4*)&Sb[(size_t)(k0 + kk) * HW + m0 + mm];
            *(float4*)&As[kk][mm] = v;
        }
        {   // B tile: W[o][i] -> transpose into Bs[i][o]
            int oo = t >> 1;
            int ko = (t & 1) * 4;
            float4 v = *(const float4*)&W[(size_t)(n0 + oo) * C + k0 + ko];
            Bs[ko + 0][oo] = v.x; Bs[ko + 1][oo] = v.y;
            Bs[ko + 2][oo] = v.z; Bs[ko + 3][oo] = v.w;
        }
        __syncthreads();
        #pragma unroll
        for (int kk = 0; kk < 8; kk++) {
            float a[8], bb[8];
            #pragma unroll
            for (int r = 0; r < 8; r++)  a[r]  = As[kk][ty * 8 + r];
            #pragma unroll
            for (int c = 0; c < 8; c++)  bb[c] = Bs[kk][c * 16 + tx];
            #pragma unroll
            for (int r = 0; r < 8; r++)
                #pragma unroll
                for (int c = 0; c < 8; c++)
                    acc[r][c] += a[r] * bb[c];
        }
        __syncthreads();
    }
    float* outp = g_sp + (size_t)b * HW * C;
    #pragma unroll
    for (int r = 0; r < 8; r++) {
        int px = m0 + ty * 8 + r;
        #pragma unroll
        for (int c = 0; c < 8; c++) {
            int o = n0 + c * 16 + tx;
            outp[(size_t)px * C + o] = acc[r][c] + bias[o];
        }
    }
}

// ---------------- 3x3 conv, 6 output channels (4 offsets + 2 attn logits), split over ci ----------------
__global__ void __launch_bounds__(256) conv6_kernel(
        const float* __restrict__ res, const float* __restrict__ style,
        const float* __restrict__ ow, const float* __restrict__ aw) {
    int tile  = blockIdx.x;   // 0..3 (2x2 tiles of 32x32)
    int b     = blockIdx.y;
    int split = blockIdx.z;
    int tx0 = (tile & 1) * 32;
    int ty0 = (tile >> 1) * 32;
    __shared__ float sh[34][35];  // stride 35 -> conflict-free
    __shared__ float wsm[54];
    int t  = threadIdx.x;
    int qx = t & 7;        // 8 quads of 4 px
    int ry = t >> 3;       // 0..31

    float acc[6][4];
    #pragma unroll
    for (int j = 0; j < 6; j++)
        #pragma unroll
        for (int q = 0; q < 4; q++) acc[j][q] = 0.f;

    int ci0 = split * (CIN / NSPLIT);
    for (int cc = 0; cc < CIN / NSPLIT; cc++) {
        int ci = ci0 + cc;
        const float* src = (ci < 256 ? res : style) + ((size_t)b * 256 + (ci & 255)) * HW;
        // halo load 34x34 with zero padding
        for (int i = t; i < 34 * 34; i += 256) {
            int hy = i / 34, hx = i - hy * 34;
            int gy = ty0 + hy - 1, gx = tx0 + hx - 1;
            float v = 0.f;
            if ((unsigned)gy < 64u && (unsigned)gx < 64u) v = src[gy * 64 + gx];
            sh[hy][hx] = v;
        }
        if (t < 54) {
            int j = t / 9, k = t - j * 9;
            wsm[t] = (j < 4) ? ow[(size_t)(j * CIN + ci) * 9 + k]
                             : aw[(size_t)((j - 4) * CIN + ci) * 9 + k];
        }
        __syncthreads();
        float pix[3][6];
        #pragma unroll
        for (int dy = 0; dy < 3; dy++)
            #pragma unroll
            for (int dx = 0; dx < 6; dx++)
                pix[dy][dx] = sh[ry + dy][qx * 4 + dx];
        #pragma unroll
        for (int j = 0; j < 6; j++)
            #pragma unroll
            for (int ky = 0; ky < 3; ky++)
                #pragma unroll
                for (int kx = 0; kx < 3; kx++) {
                    float w = wsm[j * 9 + ky * 3 + kx];
                    #pragma unroll
                    for (int q = 0; q < 4; q++)
                        acc[j][q] += w * pix[ky][kx + q];
                }
        __syncthreads();
    }
    float* dst = g_off_partial + ((size_t)split * B + b) * 6 * HW;
    #pragma unroll
    for (int j = 0; j < 6; j++)
        #pragma unroll
        for (int q = 0; q < 4; q++) {
            int gy = ty0 + ry, gx = tx0 + qx * 4 + q;
            dst[(size_t)j * HW + gy * 64 + gx] = acc[j][q];
        }
}

// ---------------- combine conv splits, add bias, sigmoid(attn), |off| partial sums ----------------
__global__ void __launch_bounds__(256) finalize_kernel(
        const float* __restrict__ ob, const float* __restrict__ ab) {
    int bc = blockIdx.x;   // 0..47
    int b = bc / 6, ch = bc - b * 6;
    float bias = (ch < 4) ? ob[ch] : ab[ch - 4];
    int t = threadIdx.x;
    float lsum = 0.f;
    for (int px = t; px < HW; px += 256) {
        float v = bias;
        #pragma unroll
        for (int s = 0; s < NSPLIT; s++)
            v += g_off_partial[(((size_t)s * B + b) * 6 + ch) * HW + px];
        if (ch < 4) {
            g_off[(size_t)(b * 4 + ch) * HW + px] = v;
            lsum += fabsf(v);
        } else {
            g_attn[(size_t)(b * 2 + (ch - 4)) * HW + px] = 1.f / (1.f + expf(-v));
        }
    }
    if (ch < 4) {
        __shared__ float red[256];
        red[t] = lsum; __syncthreads();
        for (int o = 128; o > 0; o >>= 1) {
            if (t < o) red[t] += red[t + o];
            __syncthreads();
        }
        if (t == 0) g_loss_partial[b * 4 + ch] = red[0];
    }
}

__global__ void loss_final_kernel(float* __restrict__ out, int loss_idx) {
    float s = g_loss_partial[threadIdx.x];  // 32 threads
    #pragma unroll
    for (int o = 16; o > 0; o >>= 1) s += __shfl_down_sync(0xffffffffu, s, o);
    if (threadIdx.x == 0) out[loss_idx] = s * (1.f / 131072.f);
}

// ---------------- bilinear 4-point sampling; one warp per (b,head,px) ----------------
__global__ void __launch_bounds__(256) sample_kernel(
        const float* __restrict__ Wp, const float* __restrict__ bpts) {
    int widx = blockIdx.x * 8 + (threadIdx.x >> 5);
    int lane = threadIdx.x & 31;
    int b    = widx >> 13;
    int head = (widx >> 12) & 1;
    int px   = widx & 4095;
    int py   = px >> 6;
    int pxx  = px & 63;

    float off0 = g_off[(size_t)((b * 2 + head) * 2 + 0) * HW + px];
    float off1 = g_off[(size_t)((b * 2 + head) * 2 + 1) * HW + px];
    float a    = g_attn[(size_t)(b * 2 + head) * HW + px];

    float ybase = (float)py  * (2.0f / 63.0f) - 1.0f;   // base_grid ch0 = ys[py]
    float xbase = (float)pxx * (2.0f / 63.0f) - 1.0f;   // base_grid ch1 = xs[pxx]

    const float* spb = g_sp + (size_t)b * HW * C;
    int c8 = lane * 8;
    float acc[8];
    #pragma unroll
    for (int i = 0; i < 8; i++) acc[i] = 0.f;

    #pragma unroll
    for (int p = 0; p < POINTS; p++) {
        float g0 = ybase + __ldg(&bpts[p * 2 + 0]) + off0;   // used as x in grid_sample
        float g1 = xbase + __ldg(&bpts[p * 2 + 1]) + off1;   // used as y
        float gx = (g0 + 1.f) * 0.5f * 63.f;
        float gy = (g1 + 1.f) * 0.5f * 63.f;
        float x0f = floorf(gx), y0f = floorf(gy);
        float fx = gx - x0f, fy = gy - y0f;
        float scale = __ldg(&Wp[head * POINTS + p]) * a;
        float w00 = (1.f - fx) * (1.f - fy) * scale;
        float w10 = fx * (1.f - fy) * scale;
        float w01 = (1.f - fx) * fy * scale;
        float w11 = fx * fy * scale;
        bool vx0 = (x0f >= 0.f)  && (x0f <= 63.f);
        bool vx1 = (x0f >= -1.f) && (x0f <= 62.f);
        bool vy0 = (y0f >= 0.f)  && (y0f <= 63.f);
        bool vy1 = (y0f >= -1.f) && (y0f <= 62.f);
        int xi0 = (int)x0f, yi0 = (int)y0f;

        if (vx0 && vy0) {
            const float4* p4 = (const float4*)&spb[(size_t)(yi0 * 64 + xi0) * C + c8];
            float4 v0 = p4[0], v1 = p4[1];
            acc[0] += w00 * v0.x; acc[1] += w00 * v0.y; acc[2] += w00 * v0.z; acc[3] += w00 * v0.w;
            acc[4] += w00 * v1.x; acc[5] += w00 * v1.y; acc[6] += w00 * v1.z; acc[7] += w00 * v1.w;
        }
        if (vx1 && vy0) {
            const float4* p4 = (const float4*)&spb[(size_t)(yi0 * 64 + xi0 + 1) * C + c8];
            float4 v0 = p4[0], v1 = p4[1];
            acc[0] += w10 * v0.x; acc[1] += w10 * v0.y; acc[2] += w10 * v0.z; acc[3] += w10 * v0.w;
            acc[4] += w10 * v1.x; acc[5] += w10 * v1.y; acc[6] += w10 * v1.z; acc[7] += w10 * v1.w;
        }
        if (vx0 && vy1) {
            const float4* p4 = (const float4*)&spb[(size_t)((yi0 + 1) * 64 + xi0) * C + c8];
            float4 v0 = p4[0], v1 = p4[1];
            acc[0] += w01 * v0.x; acc[1] += w01 * v0.y; acc[2] += w01 * v0.z; acc[3] += w01 * v0.w;
            acc[4] += w01 * v1.x; acc[5] += w01 * v1.y; acc[6] += w01 * v1.z; acc[7] += w01 * v1.w;
        }
        if (vx1 && vy1) {
            const float4* p4 = (const float4*)&spb[(size_t)((yi0 + 1) * 64 + xi0 + 1) * C + c8];
            float4 v0 = p4[0], v1 = p4[1];
            acc[0] += w11 * v0.x; acc[1] += w11 * v0.y; acc[2] += w11 * v0.z; acc[3] += w11 * v0.w;
            acc[4] += w11 * v1.x; acc[5] += w11 * v1.y; acc[6] += w11 * v1.z; acc[7] += w11 * v1.w;
        }
    }
    float* dst = g_hv + ((size_t)(b * HW + px) * 512 + head * 256 + c8);
    float4 o0 = make_float4(acc[0], acc[1], acc[2], acc[3]);
    float4 o1 = make_float4(acc[4], acc[5], acc[6], acc[7]);
    *(float4*)dst = o0;
    *((float4*)dst + 1) = o1;
}

// ---------------- fuse 1x1 GEMM + gate epilogue ----------------
// out[b][o][px] = alpha*(sum_j hv[b][px][j]*Fw[o][j] + fb[o]) + (1-alpha)*res[b][o][px]
__global__ void __launch_bounds__(256) fuse_gemm_kernel(
        const float* __restrict__ Fw, const float* __restrict__ fb,
        const float* __restrict__ res, float* __restrict__ out) {
    int b  = blockIdx.z;
    int m0 = blockIdx.x * 128;   // px
    int n0 = blockIdx.y * 128;   // o
    __shared__ float As[8][132];
    __shared__ float Bs[8][132];
    int t = threadIdx.x;
    int tx = t & 15, ty = t >> 4;
    float acc[8][8];
    #pragma unroll
    for (int r = 0; r < 8; r++)
        #pragma unroll
        for (int c = 0; c < 8; c++) acc[r][c] = 0.f;

    const float* Ab = g_hv + (size_t)b * HW * 512;
    for (int k0 = 0; k0 < 512; k0 += 8) {
        {   // A: hv[px][j], j contiguous -> transpose into As[k][m]
            int mm = t >> 1;
            int ko = (t & 1) * 4;
            float4 v = *(const float4*)&Ab[(size_t)(m0 + mm) * 512 + k0 + ko];
            As[ko + 0][mm] = v.x; As[ko + 1][mm] = v.y;
            As[ko + 2][mm] = v.z; As[ko + 3][mm] = v.w;
        }
        {   // B: Fw[o][j], j contiguous -> transpose into Bs[k][o]
            int oo = t >> 1;
            int ko = (t & 1) * 4;
            float4 v = *(const float4*)&Fw[(size_t)(n0 + oo) * 512 + k0 + ko];
            Bs[ko + 0][oo] = v.x; Bs[ko + 1][oo] = v.y;
            Bs[ko + 2][oo] = v.z; Bs[ko + 3][oo] = v.w;
        }
        __syncthreads();
        #pragma unroll
        for (int kk = 0; kk < 8; kk++) {
            float a[8], bb[8];
            #pragma unroll
            for (int r = 0; r < 8; r++)  a[r]  = As[kk][r * 16 + tx];
            #pragma unroll
            for (int c = 0; c < 8; c++)  bb[c] = Bs[kk][ty * 8 + c];
            #pragma unroll
            for (int r = 0; r < 8; r++)
                #pragma unroll
                for (int c = 0; c < 8; c++)
                    acc[r][c] += a[r] * bb[c];
        }
        __syncthreads();
    }
    float al = g_alpha[b];
    float ial = 1.f - al;
    #pragma unroll
    for (int c = 0; c < 8; c++) {
        int o = n0 + ty * 8 + c;
        float bia = fb[o];
        #pragma unroll
        for (int r = 0; r < 8; r++) {
            int px = m0 + r * 16 + tx;
            size_t idx = ((size_t)(b * C + o)) * HW + px;
            out[idx] = al * (acc[r][c] + bia) + ial * res[idx];
        }
    }
}

// ---------------- launch ----------------
extern "C" void kernel_launch(void* const* d_in, const int* in_sizes, int n_in,
                              void* d_out, int out_size) {
    const float* res   = (const float*)d_in[0];
    const float* style = (const float*)d_in[1];
    const float* temb  = (const float*)d_in[2];
    const float* spw   = (const float*)d_in[3];
    const float* spb   = (const float*)d_in[4];
    const float* ow    = (const float*)d_in[5];
    const float* ob    = (const float*)d_in[6];
    const float* aw    = (const float*)d_in[7];
    const float* ab    = (const float*)d_in[8];
    const float* Wp    = (const float*)d_in[9];
    const float* fw    = (const float*)d_in[10];
    const float* fb    = (const float*)d_in[11];
    const float* tw    = (const float*)d_in[12];
    const float* tb    = (const float*)d_in[13];
    const float* bpts  = (const float*)d_in[14];
    float* out = (float*)d_out;

    alpha_kernel<<<B, 256>>>(temb, tw, tb);
    style_gemm_kernel<<<dim3(32, 2, B), 256>>>(style, spw, spb);
    conv6_kernel<<<dim3(4, B, NSPLIT), 256>>>(res, style, ow, aw);
    finalize_kernel<<<48, 256>>>(ob, ab);
    loss_final_kernel<<<1, 32>>>(out, out_size - 1);
    sample_kernel<<<8192, 256>>>(Wp, bpts);
    fuse_gemm_kernel<<<dim3(32, 2, B), 256>>>(fw, fb, res, out);
}

// round 2
// speedup vs baseline: 1.6635x; 1.6635x over previous
#include <cuda_runtime.h>
#include <math.h>
#include <stdint.h>

#define B 8
#define C 256
#define HW 4096
#define HEADS 2
#define POINTS 4
#define CIN 512
#define TEMB 1024
#define NSPLIT 8

// ---------------- scratch (static device arrays; no allocation) ----------------
__device__ float g_sp[B * HW * C];            // style_proj, channels-last [b][px][c]
__device__ float g_hv[B * HW * 2 * C];        // head_vals,  channels-last [b][px][head*256+c]
__device__ float g_off_partial[NSPLIT * B * 6 * HW];
__device__ float g_off[B * 4 * HW];           // [b][head*2+d][px]
__device__ float g_attn[B * HEADS * HW];      // [b][head][px]
__device__ float g_alpha[B];
__device__ float g_loss_partial[B * 4];

// ---------------- tf32 mma helpers ----------------
__device__ __forceinline__ uint32_t f2tf(float x) {
    uint32_t r; asm("cvt.rna.tf32.f32 %0, %1;" : "=r"(r) : "f"(x)); return r;
}
__device__ __forceinline__ void mma_tf32(float c[4],
        uint32_t a0, uint32_t a1, uint32_t a2, uint32_t a3,
        uint32_t b0, uint32_t b1) {
    asm volatile(
        "mma.sync.aligned.m16n8k8.row.col.f32.tf32.tf32.f32 "
        "{%0,%1,%2,%3},{%4,%5,%6,%7},{%8,%9},{%0,%1,%2,%3};"
        : "+f"(c[0]), "+f"(c[1]), "+f"(c[2]), "+f"(c[3])
        : "r"(a0), "r"(a1), "r"(a2), "r"(a3), "r"(b0), "r"(b1));
}

// ---------------- alpha = sigmoid(silu(temb) @ tgate_w^T + tgate_b) ----------------
__global__ void alpha_kernel(const float* __restrict__ temb,
                             const float* __restrict__ tw,
                             const float* __restrict__ tb) {
    int b = blockIdx.x;
    int t = threadIdx.x;
    float s = 0.f;
    for (int k = t; k < TEMB; k += 256) {
        float x = temb[b * TEMB + k];
        float si = x / (1.f + expf(-x));   // silu
        s += si * tw[k];
    }
    __shared__ float red[256];
    red[t] = s; __syncthreads();
    for (int o = 128; o > 0; o >>= 1) {
        if (t < o) red[t] += red[t + o];
        __syncthreads();
    }
    if (t == 0) {
        float v = red[0] + tb[0];
        g_alpha[b] = 1.f / (1.f + expf(-v));
    }
}

// ---------------- style_proj GEMM (tensor cores, tf32) ----------------
// g_sp[b][px][o] = sum_i S[b][i][px]*W[o][i] + bias[o]
// M=4096(px) N=256(o) K=256. Block 128x128, 8 warps, warp tile 32x64, K-step 32.
__global__ void __launch_bounds__(256) style_gemm_tc(
        const float* __restrict__ S, const float* __restrict__ W,
        const float* __restrict__ bias) {
    int b  = blockIdx.z;
    int m0 = blockIdx.x * 128;   // px
    int n0 = blockIdx.y * 128;   // o
    __shared__ __align__(16) uint32_t As[32][136];  // [k][m]
    __shared__ __align__(16) uint32_t Bs[128][36];  // [n][k]
    int t = threadIdx.x, lane = t & 31, warp = t >> 5;
    int wm = warp >> 1, wn = warp & 1;
    int g = lane >> 2, tg = lane & 3;

    float acc[2][8][4];
    #pragma unroll
    for (int mt = 0; mt < 2; mt++)
        #pragma unroll
        for (int nt = 0; nt < 8; nt++)
            #pragma unroll
            for (int i = 0; i < 4; i++) acc[mt][nt][i] = 0.f;

    const float* Sb = S + (size_t)b * C * HW;
    int ar[4], ac[4], bn[4], bk[4];
    #pragma unroll
    for (int i = 0; i < 4; i++) {
        int id = t + i * 256;
        ar[i] = id >> 5; ac[i] = id & 31;   // A: 32 rows(k) x 32 float4(m)
        bn[i] = id >> 3; bk[i] = id & 7;    // B: 128 rows(n) x 8 float4(k)
    }

    float4 pa[4], pb[4];
    #pragma unroll
    for (int i = 0; i < 4; i++) {
        pa[i] = *(const float4*)&Sb[(size_t)ar[i] * HW + m0 + ac[i] * 4];
        pb[i] = *(const float4*)&W[(size_t)(n0 + bn[i]) * C + bk[i] * 4];
    }
    #pragma unroll
    for (int i = 0; i < 4; i++) {
        *(uint4*)&As[ar[i]][ac[i] * 4] =
            make_uint4(f2tf(pa[i].x), f2tf(pa[i].y), f2tf(pa[i].z), f2tf(pa[i].w));
        *(uint4*)&Bs[bn[i]][bk[i] * 4] =
            make_uint4(f2tf(pb[i].x), f2tf(pb[i].y), f2tf(pb[i].z), f2tf(pb[i].w));
    }
    __syncthreads();

    for (int s = 0; s < 8; s++) {
        if (s < 7) {
            int k0 = (s + 1) * 32;
            #pragma unroll
            for (int i = 0; i < 4; i++) {
                pa[i] = *(const float4*)&Sb[(size_t)(k0 + ar[i]) * HW + m0 + ac[i] * 4];
                pb[i] = *(const float4*)&W[(size_t)(n0 + bn[i]) * C + k0 + bk[i] * 4];
            }
        }
        #pragma unroll
        for (int kk = 0; kk < 4; kk++) {
            uint32_t a[2][4];
            #pragma unroll
            for (int mt = 0; mt < 2; mt++) {
                int cm = wm * 32 + mt * 16 + g;
                a[mt][0] = As[kk * 8 + tg][cm];
                a[mt][1] = As[kk * 8 + tg][cm + 8];
                a[mt][2] = As[kk * 8 + tg + 4][cm];
                a[mt][3] = As[kk * 8 + tg + 4][cm + 8];
            }
            #pragma unroll
            for (int nt = 0; nt < 8; nt++) {
                uint32_t b0 = Bs[wn * 64 + nt * 8 + g][kk * 8 + tg];
                uint32_t b1 = Bs[wn * 64 + nt * 8 + g][kk * 8 + tg + 4];
                #pragma unroll
                for (int mt = 0; mt < 2; mt++)
                    mma_tf32(acc[mt][nt], a[mt][0], a[mt][1], a[mt][2], a[mt][3], b0, b1);
            }
        }
        if (s < 7) {
            __syncthreads();
            #pragma unroll
            for (int i = 0; i < 4; i++) {
                *(uint4*)&As[ar[i]][ac[i] * 4] =
                    make_uint4(f2tf(pa[i].x), f2tf(pa[i].y), f2tf(pa[i].z), f2tf(pa[i].w));
                *(uint4*)&Bs[bn[i]][bk[i] * 4] =
                    make_uint4(f2tf(pb[i].x), f2tf(pb[i].y), f2tf(pb[i].z), f2tf(pb[i].w));
            }
            __syncthreads();
        }
    }

    float* outp = g_sp + (size_t)b * HW * C;
    #pragma unroll
    for (int nt = 0; nt < 8; nt++) {
        int o = n0 + wn * 64 + nt * 8 + tg * 2;
        float b0v = __ldg(&bias[o]), b1v = __ldg(&bias[o + 1]);
        #pragma unroll
        for (int mt = 0; mt < 2; mt++) {
            int px = m0 + wm * 32 + mt * 16 + g;
            *(float2*)&outp[(size_t)px * C + o] =
                make_float2(acc[mt][nt][0] + b0v, acc[mt][nt][1] + b1v);
            *(float2*)&outp[(size_t)(px + 8) * C + o] =
                make_float2(acc[mt][nt][2] + b0v, acc[mt][nt][3] + b1v);
        }
    }
}

// ---------------- 3x3 conv, 6 output channels, split over ci ----------------
__global__ void __launch_bounds__(256) conv6_kernel(
        const float* __restrict__ res, const float* __restrict__ style,
        const float* __restrict__ ow, const float* __restrict__ aw) {
    int tile  = blockIdx.x;   // 0..3 (2x2 tiles of 32x32)
    int b     = blockIdx.y;
    int split = blockIdx.z;
    int tx0 = (tile & 1) * 32;
    int ty0 = (tile >> 1) * 32;
    __shared__ float sh[34][35];
    __shared__ float wsm[54];
    int t  = threadIdx.x;
    int qx = t & 7;
    int ry = t >> 3;

    float acc[6][4];
    #pragma unroll
    for (int j = 0; j < 6; j++)
        #pragma unroll
        for (int q = 0; q < 4; q++) acc[j][q] = 0.f;

    int ci0 = split * (CIN / NSPLIT);
    for (int cc = 0; cc < CIN / NSPLIT; cc++) {
        int ci = ci0 + cc;
        const float* src = (ci < 256 ? res : style) + ((size_t)b * 256 + (ci & 255)) * HW;
        for (int i = t; i < 34 * 34; i += 256) {
            int hy = i / 34, hx = i - hy * 34;
            int gy = ty0 + hy - 1, gx = tx0 + hx - 1;
            float v = 0.f;
            if ((unsigned)gy < 64u && (unsigned)gx < 64u) v = src[gy * 64 + gx];
            sh[hy][hx] = v;
        }
        if (t < 54) {
            int j = t / 9, k = t - j * 9;
            wsm[t] = (j < 4) ? ow[(size_t)(j * CIN + ci) * 9 + k]
                             : aw[(size_t)((j - 4) * CIN + ci) * 9 + k];
        }
        __syncthreads();
        float pix[3][6];
        #pragma unroll
        for (int dy = 0; dy < 3; dy++)
            #pragma unroll
            for (int dx = 0; dx < 6; dx++)
                pix[dy][dx] = sh[ry + dy][qx * 4 + dx];
        #pragma unroll
        for (int j = 0; j < 6; j++)
            #pragma unroll
            for (int ky = 0; ky < 3; ky++)
                #pragma unroll
                for (int kx = 0; kx < 3; kx++) {
                    float w = wsm[j * 9 + ky * 3 + kx];
                    #pragma unroll
                    for (int q = 0; q < 4; q++)
                        acc[j][q] += w * pix[ky][kx + q];
                }
        __syncthreads();
    }
    float* dst = g_off_partial + ((size_t)split * B + b) * 6 * HW;
    #pragma unroll
    for (int j = 0; j < 6; j++)
        #pragma unroll
        for (int q = 0; q < 4; q++) {
            int gy = ty0 + ry, gx = tx0 + qx * 4 + q;
            dst[(size_t)j * HW + gy * 64 + gx] = acc[j][q];
        }
}

// ---------------- combine conv splits, add bias, sigmoid(attn), |off| partial sums ----------------
__global__ void __launch_bounds__(256) finalize_kernel(
        const float* __restrict__ ob, const float* __restrict__ ab) {
    int bc = blockIdx.x;   // 0..47
    int b = bc / 6, ch = bc - b * 6;
    float bias = (ch < 4) ? ob[ch] : ab[ch - 4];
    int t = threadIdx.x;
    float lsum = 0.f;
    for (int px = t; px < HW; px += 256) {
        float v = bias;
        #pragma unroll
        for (int s = 0; s < NSPLIT; s++)
            v += g_off_partial[(((size_t)s * B + b) * 6 + ch) * HW + px];
        if (ch < 4) {
            g_off[(size_t)(b * 4 + ch) * HW + px] = v;
            lsum += fabsf(v);
        } else {
            g_attn[(size_t)(b * 2 + (ch - 4)) * HW + px] = 1.f / (1.f + expf(-v));
        }
    }
    if (ch < 4) {
        __shared__ float red[256];
        red[t] = lsum; __syncthreads();
        for (int o = 128; o > 0; o >>= 1) {
            if (t < o) red[t] += red[t + o];
            __syncthreads();
        }
        if (t == 0) g_loss_partial[b * 4 + ch] = red[0];
    }
}

__global__ void loss_final_kernel(float* __restrict__ out, int loss_idx) {
    float s = g_loss_partial[threadIdx.x];  // 32 threads
    #pragma unroll
    for (int o = 16; o > 0; o >>= 1) s += __shfl_down_sync(0xffffffffu, s, o);
    if (threadIdx.x == 0) out[loss_idx] = s * (1.f / 131072.f);
}

// ---------------- bilinear 4-point sampling; one warp per (b,head,px) ----------------
__global__ void __launch_bounds__(256) sample_kernel(
        const float* __restrict__ Wp, const float* __restrict__ bpts) {
    int widx = blockIdx.x * 8 + (threadIdx.x >> 5);
    int lane = threadIdx.x & 31;
    int b    = widx >> 13;
    int head = (widx >> 12) & 1;
    int px   = widx & 4095;
    int py   = px >> 6;
    int pxx  = px & 63;

    float off0 = g_off[(size_t)((b * 2 + head) * 2 + 0) * HW + px];
    float off1 = g_off[(size_t)((b * 2 + head) * 2 + 1) * HW + px];
    float a    = g_attn[(size_t)(b * 2 + head) * HW + px];

    float ybase = (float)py  * (2.0f / 63.0f) - 1.0f;
    float xbase = (float)pxx * (2.0f / 63.0f) - 1.0f;

    const float* spb = g_sp + (size_t)b * HW * C;
    int c8 = lane * 8;
    float acc[8];
    #pragma unroll
    for (int i = 0; i < 8; i++) acc[i] = 0.f;

    #pragma unroll
    for (int p = 0; p < POINTS; p++) {
        float g0 = ybase + __ldg(&bpts[p * 2 + 0]) + off0;
        float g1 = xbase + __ldg(&bpts[p * 2 + 1]) + off1;
        float gx = (g0 + 1.f) * 0.5f * 63.f;
        float gy = (g1 + 1.f) * 0.5f * 63.f;
        float x0f = floorf(gx), y0f = floorf(gy);
        float fx = gx - x0f, fy = gy - y0f;
        float scale = __ldg(&Wp[head * POINTS + p]) * a;
        float w00 = (1.f - fx) * (1.f - fy) * scale;
        float w10 = fx * (1.f - fy) * scale;
        float w01 = (1.f - fx) * fy * scale;
        float w11 = fx * fy * scale;
        bool vx0 = (x0f >= 0.f)  && (x0f <= 63.f);
        bool vx1 = (x0f >= -1.f) && (x0f <= 62.f);
        bool vy0 = (y0f >= 0.f)  && (y0f <= 63.f);
        bool vy1 = (y0f >= -1.f) && (y0f <= 62.f);
        int xi0 = (int)x0f, yi0 = (int)y0f;

        if (vx0 && vy0) {
            const float4* p4 = (const float4*)&spb[(size_t)(yi0 * 64 + xi0) * C + c8];
            float4 v0 = p4[0], v1 = p4[1];
            acc[0] += w00 * v0.x; acc[1] += w00 * v0.y; acc[2] += w00 * v0.z; acc[3] += w00 * v0.w;
            acc[4] += w00 * v1.x; acc[5] += w00 * v1.y; acc[6] += w00 * v1.z; acc[7] += w00 * v1.w;
        }
        if (vx1 && vy0) {
            const float4* p4 = (const float4*)&spb[(size_t)(yi0 * 64 + xi0 + 1) * C + c8];
            float4 v0 = p4[0], v1 = p4[1];
            acc[0] += w10 * v0.x; acc[1] += w10 * v0.y; acc[2] += w10 * v0.z; acc[3] += w10 * v0.w;
            acc[4] += w10 * v1.x; acc[5] += w10 * v1.y; acc[6] += w10 * v1.z; acc[7] += w10 * v1.w;
        }
        if (vx0 && vy1) {
            const float4* p4 = (const float4*)&spb[(size_t)((yi0 + 1) * 64 + xi0) * C + c8];
            float4 v0 = p4[0], v1 = p4[1];
            acc[0] += w01 * v0.x; acc[1] += w01 * v0.y; acc[2] += w01 * v0.z; acc[3] += w01 * v0.w;
            acc[4] += w01 * v1.x; acc[5] += w01 * v1.y; acc[6] += w01 * v1.z; acc[7] += w01 * v1.w;
        }
        if (vx1 && vy1) {
            const float4* p4 = (const float4*)&spb[(size_t)((yi0 + 1) * 64 + xi0 + 1) * C + c8];
            float4 v0 = p4[0], v1 = p4[1];
            acc[0] += w11 * v0.x; acc[1] += w11 * v0.y; acc[2] += w11 * v0.z; acc[3] += w11 * v0.w;
            acc[4] += w11 * v1.x; acc[5] += w11 * v1.y; acc[6] += w11 * v1.z; acc[7] += w11 * v1.w;
        }
    }
    float* dst = g_hv + ((size_t)(b * HW + px) * 512 + head * 256 + c8);
    *(float4*)dst = make_float4(acc[0], acc[1], acc[2], acc[3]);
    *((float4*)dst + 1) = make_float4(acc[4], acc[5], acc[6], acc[7]);
}

// ---------------- fuse 1x1 GEMM (tensor cores, tf32) + gate epilogue ----------------
// out[b][o][px] = alpha*(sum_j hv[b][px][j]*Fw[o][j] + fb[o]) + (1-alpha)*res[b][o][px]
__global__ void __launch_bounds__(256) fuse_gemm_tc(
        const float* __restrict__ Fw, const float* __restrict__ fb,
        const float* __restrict__ res, float* __restrict__ out) {
    int b  = blockIdx.z;
    int m0 = blockIdx.x * 128;   // px
    int n0 = blockIdx.y * 128;   // o
    __shared__ __align__(16) uint32_t As[128][36];  // [m][k]
    __shared__ __align__(16) uint32_t Bs[128][36];  // [n][k]
    int t = threadIdx.x, lane = t & 31, warp = t >> 5;
    int wm = warp >> 1, wn = warp & 1;
    int g = lane >> 2, tg = lane & 3;

    float acc[2][8][4];
    #pragma unroll
    for (int mt = 0; mt < 2; mt++)
        #pragma unroll
        for (int nt = 0; nt < 8; nt++)
            #pragma unroll
            for (int i = 0; i < 4; i++) acc[mt][nt][i] = 0.f;

    const float* Ab = g_hv + (size_t)b * HW * 512;
    int rn[4], rk[4];
    #pragma unroll
    for (int i = 0; i < 4; i++) {
        int id = t + i * 256;
        rn[i] = id >> 3; rk[i] = id & 7;   // 128 rows x 8 float4(k)
    }

    float4 pa[4], pb[4];
    #pragma unroll
    for (int i = 0; i < 4; i++) {
        pa[i] = *(const float4*)&Ab[(size_t)(m0 + rn[i]) * 512 + rk[i] * 4];
        pb[i] = *(const float4*)&Fw[(size_t)(n0 + rn[i]) * 512 + rk[i] * 4];
    }
    #pragma unroll
    for (int i = 0; i < 4; i++) {
        *(uint4*)&As[rn[i]][rk[i] * 4] =
            make_uint4(f2tf(pa[i].x), f2tf(pa[i].y), f2tf(pa[i].z), f2tf(pa[i].w));
        *(uint4*)&Bs[rn[i]][rk[i] * 4] =
            make_uint4(f2tf(pb[i].x), f2tf(pb[i].y), f2tf(pb[i].z), f2tf(pb[i].w));
    }
    __syncthreads();

    for (int s = 0; s < 16; s++) {
        if (s < 15) {
            int k0 = (s + 1) * 32;
            #pragma unroll
            for (int i = 0; i < 4; i++) {
                pa[i] = *(const float4*)&Ab[(size_t)(m0 + rn[i]) * 512 + k0 + rk[i] * 4];
                pb[i] = *(const float4*)&Fw[(size_t)(n0 + rn[i]) * 512 + k0 + rk[i] * 4];
            }
        }
        #pragma unroll
        for (int kk = 0; kk < 4; kk++) {
            uint32_t a[2][4];
            #pragma unroll
            for (int mt = 0; mt < 2; mt++) {
                int cm = wm * 32 + mt * 16 + g;
                a[mt][0] = As[cm][kk * 8 + tg];
                a[mt][1] = As[cm + 8][kk * 8 + tg];
                a[mt][2] = As[cm][kk * 8 + tg + 4];
                a[mt][3] = As[cm + 8][kk * 8 + tg + 4];
            }
            #pragma unroll
            for (int nt = 0; nt < 8; nt++) {
                uint32_t b0 = Bs[wn * 64 + nt * 8 + g][kk * 8 + tg];
                uint32_t b1 = Bs[wn * 64 + nt * 8 + g][kk * 8 + tg + 4];
                #pragma unroll
                for (int mt = 0; mt < 2; mt++)
                    mma_tf32(acc[mt][nt], a[mt][0], a[mt][1], a[mt][2], a[mt][3], b0, b1);
            }
        }
        if (s < 15) {
            __syncthreads();
            #pragma unroll
            for (int i = 0; i < 4; i++) {
                *(uint4*)&As[rn[i]][rk[i] * 4] =
                    make_uint4(f2tf(pa[i].x), f2tf(pa[i].y), f2tf(pa[i].z), f2tf(pa[i].w));
                *(uint4*)&Bs[rn[i]][rk[i] * 4] =
                    make_uint4(f2tf(pb[i].x), f2tf(pb[i].y), f2tf(pb[i].z), f2tf(pb[i].w));
            }
            __syncthreads();
        }
    }

    float al = g_alpha[b];
    float ial = 1.f - al;
    #pragma unroll
    for (int nt = 0; nt < 8; nt++) {
        int o = n0 + wn * 64 + nt * 8 + tg * 2;
        float b0v = __ldg(&fb[o]), b1v = __ldg(&fb[o + 1]);
        #pragma unroll
        for (int mt = 0; mt < 2; mt++) {
            int px = m0 + wm * 32 + mt * 16 + g;
            size_t i00 = ((size_t)(b * C + o)) * HW + px;
            size_t i01 = ((size_t)(b * C + o + 1)) * HW + px;
            out[i00]     = al * (acc[mt][nt][0] + b0v) + ial * res[i00];
            out[i01]     = al * (acc[mt][nt][1] + b1v) + ial * res[i01];
            out[i00 + 8] = al * (acc[mt][nt][2] + b0v) + ial * res[i00 + 8];
            out[i01 + 8] = al * (acc[mt][nt][3] + b1v) + ial * res[i01 + 8];
        }
    }
}

// ---------------- launch ----------------
extern "C" void kernel_launch(void* const* d_in, const int* in_sizes, int n_in,
                              void* d_out, int out_size) {
    const float* res   = (const float*)d_in[0];
    const float* style = (const float*)d_in[1];
    const float* temb  = (const float*)d_in[2];
    const float* spw   = (const float*)d_in[3];
    const float* spb   = (const float*)d_in[4];
    const float* ow    = (const float*)d_in[5];
    const float* ob    = (const float*)d_in[6];
    const float* aw    = (const float*)d_in[7];
    const float* ab    = (const float*)d_in[8];
    const float* Wp    = (const float*)d_in[9];
    const float* fw    = (const float*)d_in[10];
    const float* fb    = (const float*)d_in[11];
    const float* tw    = (const float*)d_in[12];
    const float* tb    = (const float*)d_in[13];
    const float* bpts  = (const float*)d_in[14];
    float* out = (float*)d_out;

    alpha_kernel<<<B, 256>>>(temb, tw, tb);
    style_gemm_tc<<<dim3(32, 2, B), 256>>>(style, spw, spb);
    conv6_kernel<<<dim3(4, B, NSPLIT), 256>>>(res, style, ow, aw);
    finalize_kernel<<<48, 256>>>(ob, ab);
    loss_final_kernel<<<1, 32>>>(out, out_size - 1);
    sample_kernel<<<8192, 256>>>(Wp, bpts);
    fuse_gemm_tc<<<dim3(32, 2, B), 256>>>(fw, fb, res, out);
}

// round 3
// speedup vs baseline: 2.9010x; 1.7440x over previous
#include <cuda_runtime.h>
#include <cuda_bf16.h>
#include <math.h>
#include <stdint.h>

#define B 8
#define C 256
#define HW 4096
#define HEADS 2
#define POINTS 4
#define CIN 512
#define TEMB 1024
#define NSPLIT 16

// ---------------- scratch (static device arrays; no allocation) ----------------
__device__ __align__(16) __nv_bfloat16 g_sp[B * HW * C];       // style_proj, channels-last
__device__ __align__(16) __nv_bfloat16 g_hv[B * HW * 2 * C];   // head_vals, channels-last
__device__ float g_off_partial[NSPLIT * B * 6 * HW];
__device__ float g_off[B * 4 * HW];
__device__ float g_attn[B * HEADS * HW];
__device__ float g_alpha[B];
__device__ float g_loss_partial[B * 4 * 8];

// ---------------- mma helpers ----------------
__device__ __forceinline__ uint32_t f2tf(float x) {
    uint32_t r; asm("cvt.rna.tf32.f32 %0, %1;" : "=r"(r) : "f"(x)); return r;
}
__device__ __forceinline__ void mma_tf32(float c[4],
        uint32_t a0, uint32_t a1, uint32_t a2, uint32_t a3,
        uint32_t b0, uint32_t b1) {
    asm volatile(
        "mma.sync.aligned.m16n8k8.row.col.f32.tf32.tf32.f32 "
        "{%0,%1,%2,%3},{%4,%5,%6,%7},{%8,%9},{%0,%1,%2,%3};"
        : "+f"(c[0]), "+f"(c[1]), "+f"(c[2]), "+f"(c[3])
        : "r"(a0), "r"(a1), "r"(a2), "r"(a3), "r"(b0), "r"(b1));
}
__device__ __forceinline__ void mma_bf16(float c[4],
        uint32_t a0, uint32_t a1, uint32_t a2, uint32_t a3,
        uint32_t b0, uint32_t b1) {
    asm volatile(
        "mma.sync.aligned.m16n8k16.row.col.f32.bf16.bf16.f32 "
        "{%0,%1,%2,%3},{%4,%5,%6,%7},{%8,%9},{%0,%1,%2,%3};"
        : "+f"(c[0]), "+f"(c[1]), "+f"(c[2]), "+f"(c[3])
        : "r"(a0), "r"(a1), "r"(a2), "r"(a3), "r"(b0), "r"(b1));
}
__device__ __forceinline__ uint32_t packbf(float a, float b) {
    __nv_bfloat162 h = __floats2bfloat162_rn(a, b);
    return *(uint32_t*)&h;
}

// ---------------- alpha ----------------
__global__ void alpha_kernel(const float* __restrict__ temb,
                             const float* __restrict__ tw,
                             const float* __restrict__ tb) {
    int b = blockIdx.x;
    int t = threadIdx.x;
    float s = 0.f;
    for (int k = t; k < TEMB; k += 256) {
        float x = temb[b * TEMB + k];
        s += (x / (1.f + expf(-x))) * tw[k];
    }
    __shared__ float red[256];
    red[t] = s; __syncthreads();
    for (int o = 128; o > 0; o >>= 1) {
        if (t < o) red[t] += red[t + o];
        __syncthreads();
    }
    if (t == 0) g_alpha[b] = 1.f / (1.f + expf(-(red[0] + tb[0])));
}

// ---------------- style_proj GEMM (tf32 tensor cores, bf16 output) ----------------
__global__ void __launch_bounds__(256) style_gemm_tc(
        const float* __restrict__ S, const float* __restrict__ W,
        const float* __restrict__ bias) {
    int b  = blockIdx.z;
    int m0 = blockIdx.x * 128;
    int n0 = blockIdx.y * 128;
    __shared__ __align__(16) uint32_t As[32][136];  // [k][m]
    __shared__ __align__(16) uint32_t Bs[128][36];  // [n][k]
    int t = threadIdx.x, lane = t & 31, warp = t >> 5;
    int wm = warp >> 1, wn = warp & 1;
    int g = lane >> 2, tg = lane & 3;

    float acc[2][8][4];
    #pragma unroll
    for (int mt = 0; mt < 2; mt++)
        #pragma unroll
        for (int nt = 0; nt < 8; nt++)
            #pragma unroll
            for (int i = 0; i < 4; i++) acc[mt][nt][i] = 0.f;

    const float* Sb = S + (size_t)b * C * HW;
    int ar[4], ac[4], bn[4], bk[4];
    #pragma unroll
    for (int i = 0; i < 4; i++) {
        int id = t + i * 256;
        ar[i] = id >> 5; ac[i] = id & 31;
        bn[i] = id >> 3; bk[i] = id & 7;
    }

    float4 pa[4], pb[4];
    #pragma unroll
    for (int i = 0; i < 4; i++) {
        pa[i] = *(const float4*)&Sb[(size_t)ar[i] * HW + m0 + ac[i] * 4];
        pb[i] = *(const float4*)&W[(size_t)(n0 + bn[i]) * C + bk[i] * 4];
    }
    #pragma unroll
    for (int i = 0; i < 4; i++) {
        *(uint4*)&As[ar[i]][ac[i] * 4] =
            make_uint4(f2tf(pa[i].x), f2tf(pa[i].y), f2tf(pa[i].z), f2tf(pa[i].w));
        *(uint4*)&Bs[bn[i]][bk[i] * 4] =
            make_uint4(f2tf(pb[i].x), f2tf(pb[i].y), f2tf(pb[i].z), f2tf(pb[i].w));
    }
    __syncthreads();

    for (int s = 0; s < 8; s++) {
        if (s < 7) {
            int k0 = (s + 1) * 32;
            #pragma unroll
            for (int i = 0; i < 4; i++) {
                pa[i] = *(const float4*)&Sb[(size_t)(k0 + ar[i]) * HW + m0 + ac[i] * 4];
                pb[i] = *(const float4*)&W[(size_t)(n0 + bn[i]) * C + k0 + bk[i] * 4];
            }
        }
        #pragma unroll
        for (int kk = 0; kk < 4; kk++) {
            uint32_t a[2][4];
            #pragma unroll
            for (int mt = 0; mt < 2; mt++) {
                int cm = wm * 32 + mt * 16 + g;
                a[mt][0] = As[kk * 8 + tg][cm];
                a[mt][1] = As[kk * 8 + tg][cm + 8];
                a[mt][2] = As[kk * 8 + tg + 4][cm];
                a[mt][3] = As[kk * 8 + tg + 4][cm + 8];
            }
            #pragma unroll
            for (int nt = 0; nt < 8; nt++) {
                uint32_t b0 = Bs[wn * 64 + nt * 8 + g][kk * 8 + tg];
                uint32_t b1 = Bs[wn * 64 + nt * 8 + g][kk * 8 + tg + 4];
                #pragma unroll
                for (int mt = 0; mt < 2; mt++)
                    mma_tf32(acc[mt][nt], a[mt][0], a[mt][1], a[mt][2], a[mt][3], b0, b1);
            }
        }
        if (s < 7) {
            __syncthreads();
            #pragma unroll
            for (int i = 0; i < 4; i++) {
                *(uint4*)&As[ar[i]][ac[i] * 4] =
                    make_uint4(f2tf(pa[i].x), f2tf(pa[i].y), f2tf(pa[i].z), f2tf(pa[i].w));
                *(uint4*)&Bs[bn[i]][bk[i] * 4] =
                    make_uint4(f2tf(pb[i].x), f2tf(pb[i].y), f2tf(pb[i].z), f2tf(pb[i].w));
            }
            __syncthreads();
        }
    }

    __nv_bfloat16* outp = g_sp + (size_t)b * HW * C;
    #pragma unroll
    for (int nt = 0; nt < 8; nt++) {
        int o = n0 + wn * 64 + nt * 8 + tg * 2;
        float b0v = __ldg(&bias[o]), b1v = __ldg(&bias[o + 1]);
        #pragma unroll
        for (int mt = 0; mt < 2; mt++) {
            int px = m0 + wm * 32 + mt * 16 + g;
            *(uint32_t*)&outp[(size_t)px * C + o] =
                packbf(acc[mt][nt][0] + b0v, acc[mt][nt][1] + b1v);
            *(uint32_t*)&outp[(size_t)(px + 8) * C + o] =
                packbf(acc[mt][nt][2] + b0v, acc[mt][nt][3] + b1v);
        }
    }
}

// ---------------- 3x3 conv, 6 outs, 32 ch per block, software-pipelined ----------------
__global__ void __launch_bounds__(256) conv6_kernel(
        const float* __restrict__ res, const float* __restrict__ style,
        const float* __restrict__ ow, const float* __restrict__ aw) {
    int tile  = blockIdx.x;
    int b     = blockIdx.y;
    int split = blockIdx.z;
    int tx0 = (tile & 1) * 32;
    int ty0 = (tile >> 1) * 32;
    __shared__ float sh[34 * 35];
    __shared__ float wsm[54];
    int t  = threadIdx.x;
    int qx = t & 7;
    int ry = t >> 3;

    // precompute halo slots (constant across channels)
    int goff[5], soff[5]; bool gval[5]; int ns = 0;
    #pragma unroll
    for (int s = 0; s < 5; s++) {
        int i = t + s * 256;
        if (i < 34 * 34) {
            int hy = i / 34, hx = i - hy * 34;
            int gy = ty0 + hy - 1, gx = tx0 + hx - 1;
            gval[s] = ((unsigned)gy < 64u) && ((unsigned)gx < 64u);
            goff[s] = gy * 64 + gx;
            soff[s] = hy * 35 + hx;
            ns = s + 1;
        }
    }
    int ci0 = split * 32;
    const float* base = (ci0 < 256 ? res : style) + ((size_t)b * 256 + (ci0 & 255)) * HW;
    bool wv_t = t < 54;
    int j = t / 9, k = t - j * 9;
    const float* wbase = wv_t ? ((j < 4) ? &ow[((size_t)j * CIN + ci0) * 9 + k]
                                         : &aw[((size_t)(j - 4) * CIN + ci0) * 9 + k])
                              : ow;

    float acc[6][4];
    #pragma unroll
    for (int jj = 0; jj < 6; jj++)
        #pragma unroll
        for (int q = 0; q < 4; q++) acc[jj][q] = 0.f;

    float v[5]; float wv = 0.f;
    for (int s = 0; s < ns; s++) v[s] = gval[s] ? base[goff[s]] : 0.f;
    if (wv_t) wv = wbase[0];

    for (int cc = 0; cc < 32; cc++) {
        for (int s = 0; s < ns; s++) sh[soff[s]] = v[s];
        if (wv_t) wsm[t] = wv;
        __syncthreads();
        if (cc < 31) {
            const float* src = base + (size_t)(cc + 1) * HW;
            for (int s = 0; s < ns; s++) v[s] = gval[s] ? src[goff[s]] : 0.f;
            if (wv_t) wv = wbase[(size_t)(cc + 1) * 9];
        }
        float pix[3][6];
        #pragma unroll
        for (int dy = 0; dy < 3; dy++)
            #pragma unroll
            for (int dx = 0; dx < 6; dx++)
                pix[dy][dx] = sh[(ry + dy) * 35 + qx * 4 + dx];
        #pragma unroll
        for (int jj = 0; jj < 6; jj++)
            #pragma unroll
            for (int ky = 0; ky < 3; ky++)
                #pragma unroll
                for (int kx = 0; kx < 3; kx++) {
                    float w = wsm[jj * 9 + ky * 3 + kx];
                    #pragma unroll
                    for (int q = 0; q < 4; q++)
                        acc[jj][q] += w * pix[ky][kx + q];
                }
        __syncthreads();
    }
    float* dst = g_off_partial + ((size_t)split * B + b) * 6 * HW;
    #pragma unroll
    for (int jj = 0; jj < 6; jj++)
        #pragma unroll
        for (int q = 0; q < 4; q++) {
            int gy = ty0 + ry, gx = tx0 + qx * 4 + q;
            dst[(size_t)jj * HW + gy * 64 + gx] = acc[jj][q];
        }
}

// ---------------- combine splits, bias, sigmoid, |off| partials ----------------
__global__ void __launch_bounds__(256) finalize_kernel(
        const float* __restrict__ ob, const float* __restrict__ ab) {
    int bc = blockIdx.x;          // 0..47
    int chunk = blockIdx.y;       // 0..7
    int b = bc / 6, ch = bc - b * 6;
    float bias = (ch < 4) ? ob[ch] : ab[ch - 4];
    int t = threadIdx.x;
    float lsum = 0.f;
    for (int px = chunk * 512 + t; px < (chunk + 1) * 512; px += 256) {
        float v = bias;
        #pragma unroll
        for (int s = 0; s < NSPLIT; s++)
            v += g_off_partial[(((size_t)s * B + b) * 6 + ch) * HW + px];
        if (ch < 4) {
            g_off[(size_t)(b * 4 + ch) * HW + px] = v;
            lsum += fabsf(v);
        } else {
            g_attn[(size_t)(b * 2 + (ch - 4)) * HW + px] = 1.f / (1.f + expf(-v));
        }
    }
    if (ch < 4) {
        __shared__ float red[256];
        red[t] = lsum; __syncthreads();
        for (int o = 128; o > 0; o >>= 1) {
            if (t < o) red[t] += red[t + o];
            __syncthreads();
        }
        if (t == 0) g_loss_partial[(b * 4 + ch) * 8 + chunk] = red[0];
    }
}

__global__ void loss_final_kernel(float* __restrict__ out, int loss_idx) {
    int t = threadIdx.x;
    __shared__ float red[256];
    red[t] = g_loss_partial[t];
    __syncthreads();
    for (int o = 128; o > 0; o >>= 1) {
        if (t < o) red[t] += red[t + o];
        __syncthreads();
    }
    if (t == 0) out[loss_idx] = red[0] * (1.f / 131072.f);
}

// ---------------- bilinear 4-point sampling (bf16 gathers) ----------------
__global__ void __launch_bounds__(256) sample_kernel(
        const float* __restrict__ Wp, const float* __restrict__ bpts) {
    int widx = blockIdx.x * 8 + (threadIdx.x >> 5);
    int lane = threadIdx.x & 31;
    int b    = widx >> 13;
    int head = (widx >> 12) & 1;
    int px   = widx & 4095;
    int py   = px >> 6;
    int pxx  = px & 63;

    float off0 = g_off[(size_t)((b * 2 + head) * 2 + 0) * HW + px];
    float off1 = g_off[(size_t)((b * 2 + head) * 2 + 1) * HW + px];
    float a    = g_attn[(size_t)(b * 2 + head) * HW + px];

    float ybase = (float)py  * (2.0f / 63.0f) - 1.0f;
    float xbase = (float)pxx * (2.0f / 63.0f) - 1.0f;

    const __nv_bfloat16* spb = g_sp + (size_t)b * HW * C;
    int c8 = lane * 8;
    float acc[8];
    #pragma unroll
    for (int i = 0; i < 8; i++) acc[i] = 0.f;

    #pragma unroll
    for (int p = 0; p < POINTS; p++) {
        float g0 = ybase + __ldg(&bpts[p * 2 + 0]) + off0;
        float g1 = xbase + __ldg(&bpts[p * 2 + 1]) + off1;
        float gx = (g0 + 1.f) * 0.5f * 63.f;
        float gy = (g1 + 1.f) * 0.5f * 63.f;
        float x0f = floorf(gx), y0f = floorf(gy);
        float fx = gx - x0f, fy = gy - y0f;
        float scale = __ldg(&Wp[head * POINTS + p]) * a;
        float w00 = (1.f - fx) * (1.f - fy) * scale;
        float w10 = fx * (1.f - fy) * scale;
        float w01 = (1.f - fx) * fy * scale;
        float w11 = fx * fy * scale;
        bool vx0 = (x0f >= 0.f)  && (x0f <= 63.f);
        bool vx1 = (x0f >= -1.f) && (x0f <= 62.f);
        bool vy0 = (y0f >= 0.f)  && (y0f <= 63.f);
        bool vy1 = (y0f >= -1.f) && (y0f <= 62.f);
        int xi0 = (int)x0f, yi0 = (int)y0f;

        #pragma unroll
        for (int corner = 0; corner < 4; corner++) {
            int cy = corner >> 1, cx = corner & 1;
            bool ok = (cx ? vx1 : vx0) && (cy ? vy1 : vy0);
            float w = cx ? (cy ? w11 : w10) : (cy ? w01 : w00);
            if (ok) {
                uint4 u = *(const uint4*)&spb[(size_t)((yi0 + cy) * 64 + xi0 + cx) * C + c8];
                const __nv_bfloat162* h = (const __nv_bfloat162*)&u;
                #pragma unroll
                for (int i = 0; i < 4; i++) {
                    float2 f = __bfloat1622float2(h[i]);
                    acc[i * 2]     += w * f.x;
                    acc[i * 2 + 1] += w * f.y;
                }
            }
        }
    }
    __nv_bfloat16* dst = g_hv + ((size_t)(b * HW + px) * 512 + head * 256 + c8);
    uint4 o;
    __nv_bfloat162* oh = (__nv_bfloat162*)&o;
    #pragma unroll
    for (int i = 0; i < 4; i++)
        oh[i] = __floats2bfloat162_rn(acc[i * 2], acc[i * 2 + 1]);
    *(uint4*)dst = o;
}

// ---------------- fuse 1x1 GEMM (bf16 tensor cores) + gate epilogue ----------------
#define KP 40   // smem row stride in halves
__global__ void __launch_bounds__(256) fuse_gemm_bf16(
        const float* __restrict__ Fw, const float* __restrict__ fb,
        const float* __restrict__ res, float* __restrict__ out) {
    int b  = blockIdx.z;
    int m0 = blockIdx.x * 128;   // px
    int n0 = blockIdx.y * 128;   // o
    __shared__ __align__(16) __nv_bfloat16 As[128 * KP];
    __shared__ __align__(16) __nv_bfloat16 Bs[128 * KP];
    int t = threadIdx.x, lane = t & 31, warp = t >> 5;
    int wm = warp >> 1, wn = warp & 1;
    int g = lane >> 2, tg = lane & 3;

    float acc[2][8][4];
    #pragma unroll
    for (int mt = 0; mt < 2; mt++)
        #pragma unroll
        for (int nt = 0; nt < 8; nt++)
            #pragma unroll
            for (int i = 0; i < 4; i++) acc[mt][nt][i] = 0.f;

    const __nv_bfloat16* Ab = g_hv + (size_t)b * HW * 512;

    // A: 2 uint4 (8 halves) per thread; B: 4 float4 per thread (convert)
    int arn[2], ark[2], brn[4], brk[4];
    #pragma unroll
    for (int i = 0; i < 2; i++) { int id = t + i * 256; arn[i] = id >> 2; ark[i] = id & 3; }
    #pragma unroll
    for (int i = 0; i < 4; i++) { int id = t + i * 256; brn[i] = id >> 3; brk[i] = id & 7; }

    uint4 pa[2]; float4 pb[4];
    #pragma unroll
    for (int i = 0; i < 2; i++)
        pa[i] = *(const uint4*)&Ab[(size_t)(m0 + arn[i]) * 512 + ark[i] * 8];
    #pragma unroll
    for (int i = 0; i < 4; i++)
        pb[i] = *(const float4*)&Fw[(size_t)(n0 + brn[i]) * 512 + brk[i] * 4];

    #pragma unroll
    for (int i = 0; i < 2; i++) {
        *(uint2*)&As[arn[i] * KP + ark[i] * 8]     = make_uint2(pa[i].x, pa[i].y);
        *(uint2*)&As[arn[i] * KP + ark[i] * 8 + 4] = make_uint2(pa[i].z, pa[i].w);
    }
    #pragma unroll
    for (int i = 0; i < 4; i++)
        *(uint2*)&Bs[brn[i] * KP + brk[i] * 4] =
            make_uint2(packbf(pb[i].x, pb[i].y), packbf(pb[i].z, pb[i].w));
    __syncthreads();

    for (int s = 0; s < 16; s++) {
        if (s < 15) {
            int k0 = (s + 1) * 32;
            #pragma unroll
            for (int i = 0; i < 2; i++)
                pa[i] = *(const uint4*)&Ab[(size_t)(m0 + arn[i]) * 512 + k0 + ark[i] * 8];
            #pragma unroll
            for (int i = 0; i < 4; i++)
                pb[i] = *(const float4*)&Fw[(size_t)(n0 + brn[i]) * 512 + k0 + brk[i] * 4];
        }
        #pragma unroll
        for (int kk = 0; kk < 2; kk++) {
            uint32_t a[2][4];
            #pragma unroll
            for (int mt = 0; mt < 2; mt++) {
                int cm = (wm * 32 + mt * 16 + g) * KP + kk * 16 + tg * 2;
                a[mt][0] = *(uint32_t*)&As[cm];
                a[mt][1] = *(uint32_t*)&As[cm + 8 * KP];
                a[mt][2] = *(uint32_t*)&As[cm + 8];
                a[mt][3] = *(uint32_t*)&As[cm + 8 * KP + 8];
            }
            #pragma unroll
            for (int nt = 0; nt < 8; nt++) {
                int cn = (wn * 64 + nt * 8 + g) * KP + kk * 16 + tg * 2;
                uint32_t b0 = *(uint32_t*)&Bs[cn];
                uint32_t b1 = *(uint32_t*)&Bs[cn + 8];
                #pragma unroll
                for (int mt = 0; mt < 2; mt++)
                    mma_bf16(acc[mt][nt], a[mt][0], a[mt][1], a[mt][2], a[mt][3], b0, b1);
            }
        }
        if (s < 15) {
            __syncthreads();
            #pragma unroll
            for (int i = 0; i < 2; i++) {
                *(uint2*)&As[arn[i] * KP + ark[i] * 8]     = make_uint2(pa[i].x, pa[i].y);
                *(uint2*)&As[arn[i] * KP + ark[i] * 8 + 4] = make_uint2(pa[i].z, pa[i].w);
            }
            #pragma unroll
            for (int i = 0; i < 4; i++)
                *(uint2*)&Bs[brn[i] * KP + brk[i] * 4] =
                    make_uint2(packbf(pb[i].x, pb[i].y), packbf(pb[i].z, pb[i].w));
            __syncthreads();
        }
    }

    float al = g_alpha[b];
    float ial = 1.f - al;
    #pragma unroll
    for (int nt = 0; nt < 8; nt++) {
        int o = n0 + wn * 64 + nt * 8 + tg * 2;
        float b0v = __ldg(&fb[o]), b1v = __ldg(&fb[o + 1]);
        #pragma unroll
        for (int mt = 0; mt < 2; mt++) {
            int px = m0 + wm * 32 + mt * 16 + g;
            size_t i00 = ((size_t)(b * C + o)) * HW + px;
            size_t i01 = ((size_t)(b * C + o + 1)) * HW + px;
            out[i00]     = al * (acc[mt][nt][0] + b0v) + ial * res[i00];
            out[i01]     = al * (acc[mt][nt][1] + b1v) + ial * res[i01];
            out[i00 + 8] = al * (acc[mt][nt][2] + b0v) + ial * res[i00 + 8];
            out[i01 + 8] = al * (acc[mt][nt][3] + b1v) + ial * res[i01 + 8];
        }
    }
}

// ---------------- launch ----------------
extern "C" void kernel_launch(void* const* d_in, const int* in_sizes, int n_in,
                              void* d_out, int out_size) {
    const float* res   = (const float*)d_in[0];
    const float* style = (const float*)d_in[1];
    const float* temb  = (const float*)d_in[2];
    const float* spw   = (const float*)d_in[3];
    const float* spb   = (const float*)d_in[4];
    const float* ow    = (const float*)d_in[5];
    const float* ob    = (const float*)d_in[6];
    const float* aw    = (const float*)d_in[7];
    const float* ab    = (const float*)d_in[8];
    const float* Wp    = (const float*)d_in[9];
    const float* fw    = (const float*)d_in[10];
    const float* fb    = (const float*)d_in[11];
    const float* tw    = (const float*)d_in[12];
    const float* tb    = (const float*)d_in[13];
    const float* bpts  = (const float*)d_in[14];
    float* out = (float*)d_out;

    alpha_kernel<<<B, 256>>>(temb, tw, tb);
    style_gemm_tc<<<dim3(32, 2, B), 256>>>(style, spw, spb);
    conv6_kernel<<<dim3(4, B, NSPLIT), 256>>>(res, style, ow, aw);
    finalize_kernel<<<dim3(48, 8), 256>>>(ob, ab);
    loss_final_kernel<<<1, 256>>>(out, out_size - 1);
    sample_kernel<<<8192, 256>>>(Wp, bpts);
    fuse_gemm_bf16<<<dim3(32, 2, B), 256>>>(fw, fb, res, out);
}

// round 5
// speedup vs baseline: 3.1368x; 1.0813x over previous
#include <cuda_runtime.h>
#include <cuda_bf16.h>
#include <math.h>
#include <stdint.h>

#define B 8
#define C 256
#define HW 4096
#define HEADS 2
#define POINTS 4
#define CIN 512
#define TEMB 1024
#define NSPLIT 16

// ---------------- scratch ----------------
__device__ __align__(16) __nv_bfloat16 g_sp[B * HW * C];
__device__ __align__(16) __nv_bfloat16 g_hv[B * HW * 2 * C];
__device__ float g_off_partial[NSPLIT * B * 6 * HW];
__device__ float g_off[B * 4 * HW];
__device__ float g_attn[B * HEADS * HW];
__device__ float g_alpha[B];
__device__ float g_loss_partial[B * 4 * 8];

// ---------------- mma helpers ----------------
__device__ __forceinline__ uint32_t f2tf(float x) {
    uint32_t r; asm("cvt.rna.tf32.f32 %0, %1;" : "=r"(r) : "f"(x)); return r;
}
__device__ __forceinline__ void mma_tf32(float c[4],
        uint32_t a0, uint32_t a1, uint32_t a2, uint32_t a3,
        uint32_t b0, uint32_t b1) {
    asm volatile(
        "mma.sync.aligned.m16n8k8.row.col.f32.tf32.tf32.f32 "
        "{%0,%1,%2,%3},{%4,%5,%6,%7},{%8,%9},{%0,%1,%2,%3};"
        : "+f"(c[0]), "+f"(c[1]), "+f"(c[2]), "+f"(c[3])
        : "r"(a0), "r"(a1), "r"(a2), "r"(a3), "r"(b0), "r"(b1));
}
__device__ __forceinline__ void mma_bf16(float c[4],
        uint32_t a0, uint32_t a1, uint32_t a2, uint32_t a3,
        uint32_t b0, uint32_t b1) {
    asm volatile(
        "mma.sync.aligned.m16n8k16.row.col.f32.bf16.bf16.f32 "
        "{%0,%1,%2,%3},{%4,%5,%6,%7},{%8,%9},{%0,%1,%2,%3};"
        : "+f"(c[0]), "+f"(c[1]), "+f"(c[2]), "+f"(c[3])
        : "r"(a0), "r"(a1), "r"(a2), "r"(a3), "r"(b0), "r"(b1));
}
__device__ __forceinline__ uint32_t packbf(float a, float b) {
    __nv_bfloat162 h = __floats2bfloat162_rn(a, b);
    return *(uint32_t*)&h;
}

// ================= heterogeneous front kernel =================
// blocks [0,512)    : style GEMM (tf32 tensor cores)
// blocks [512,1024) : conv6 3x3 (FMA pipe)
// blocks [1024,1032): alpha
__global__ void __launch_bounds__(256) front_kernel(
        const float* __restrict__ S, const float* __restrict__ W,
        const float* __restrict__ bias,
        const float* __restrict__ res, const float* __restrict__ ow,
        const float* __restrict__ aw,
        const float* __restrict__ temb, const float* __restrict__ tw,
        const float* __restrict__ tb) {
    __shared__ union {
        struct { uint32_t As[32][136]; uint32_t Bs[128][36]; } s;
        struct { float sh[34 * 35]; float wsm[54]; } cv;
        float red[256];
    } u;
    int blk = blockIdx.x;
    int t = threadIdx.x;

    if (blk < 512) {
        // ---------------- style GEMM ----------------
        int b  = blk >> 6;
        int m0 = (blk & 31) * 128;
        int n0 = ((blk >> 5) & 1) * 128;
        int lane = t & 31, warp = t >> 5;
        int wm = warp >> 1, wn = warp & 1;
        int g = lane >> 2, tg = lane & 3;

        float acc[2][8][4];
        #pragma unroll
        for (int mt = 0; mt < 2; mt++)
            #pragma unroll
            for (int nt = 0; nt < 8; nt++)
                #pragma unroll
                for (int i = 0; i < 4; i++) acc[mt][nt][i] = 0.f;

        const float* Sb = S + (size_t)b * C * HW;
        int ar[4], ac[4], bn[4], bk[4];
        #pragma unroll
        for (int i = 0; i < 4; i++) {
            int id = t + i * 256;
            ar[i] = id >> 5; ac[i] = id & 31;
            bn[i] = id >> 3; bk[i] = id & 7;
        }
        float4 pa[4], pb[4];
        #pragma unroll
        for (int i = 0; i < 4; i++) {
            pa[i] = *(const float4*)&Sb[(size_t)ar[i] * HW + m0 + ac[i] * 4];
            pb[i] = *(const float4*)&W[(size_t)(n0 + bn[i]) * C + bk[i] * 4];
        }
        #pragma unroll
        for (int i = 0; i < 4; i++) {
            *(uint4*)&u.s.As[ar[i]][ac[i] * 4] =
                make_uint4(f2tf(pa[i].x), f2tf(pa[i].y), f2tf(pa[i].z), f2tf(pa[i].w));
            *(uint4*)&u.s.Bs[bn[i]][bk[i] * 4] =
                make_uint4(f2tf(pb[i].x), f2tf(pb[i].y), f2tf(pb[i].z), f2tf(pb[i].w));
        }
        __syncthreads();

        for (int s = 0; s < 8; s++) {
            if (s < 7) {
                int k0 = (s + 1) * 32;
                #pragma unroll
                for (int i = 0; i < 4; i++) {
                    pa[i] = *(const float4*)&Sb[(size_t)(k0 + ar[i]) * HW + m0 + ac[i] * 4];
                    pb[i] = *(const float4*)&W[(size_t)(n0 + bn[i]) * C + k0 + bk[i] * 4];
                }
            }
            #pragma unroll
            for (int kk = 0; kk < 4; kk++) {
                uint32_t a[2][4];
                #pragma unroll
                for (int mt = 0; mt < 2; mt++) {
                    int cm = wm * 32 + mt * 16 + g;
                    a[mt][0] = u.s.As[kk * 8 + tg][cm];
                    a[mt][1] = u.s.As[kk * 8 + tg][cm + 8];
                    a[mt][2] = u.s.As[kk * 8 + tg + 4][cm];
                    a[mt][3] = u.s.As[kk * 8 + tg + 4][cm + 8];
                }
                #pragma unroll
                for (int nt = 0; nt < 8; nt++) {
                    uint32_t b0 = u.s.Bs[wn * 64 + nt * 8 + g][kk * 8 + tg];
                    uint32_t b1 = u.s.Bs[wn * 64 + nt * 8 + g][kk * 8 + tg + 4];
                    #pragma unroll
                    for (int mt = 0; mt < 2; mt++)
                        mma_tf32(acc[mt][nt], a[mt][0], a[mt][1], a[mt][2], a[mt][3], b0, b1);
                }
            }
            if (s < 7) {
                __syncthreads();
                #pragma unroll
                for (int i = 0; i < 4; i++) {
                    *(uint4*)&u.s.As[ar[i]][ac[i] * 4] =
                        make_uint4(f2tf(pa[i].x), f2tf(pa[i].y), f2tf(pa[i].z), f2tf(pa[i].w));
                    *(uint4*)&u.s.Bs[bn[i]][bk[i] * 4] =
                        make_uint4(f2tf(pb[i].x), f2tf(pb[i].y), f2tf(pb[i].z), f2tf(pb[i].w));
                }
                __syncthreads();
            }
        }
        __nv_bfloat16* outp = g_sp + (size_t)b * HW * C;
        #pragma unroll
        for (int nt = 0; nt < 8; nt++) {
            int o = n0 + wn * 64 + nt * 8 + tg * 2;
            float b0v = __ldg(&bias[o]), b1v = __ldg(&bias[o + 1]);
            #pragma unroll
            for (int mt = 0; mt < 2; mt++) {
                int px = m0 + wm * 32 + mt * 16 + g;
                *(uint32_t*)&outp[(size_t)px * C + o] =
                    packbf(acc[mt][nt][0] + b0v, acc[mt][nt][1] + b1v);
                *(uint32_t*)&outp[(size_t)(px + 8) * C + o] =
                    packbf(acc[mt][nt][2] + b0v, acc[mt][nt][3] + b1v);
            }
        }
    } else if (blk < 1024) {
        // ---------------- conv6 ----------------
        int c0 = blk - 512;
        int tile  = c0 & 3;
        int b     = (c0 >> 2) & 7;
        int split = c0 >> 5;
        int tx0 = (tile & 1) * 32;
        int ty0 = (tile >> 1) * 32;
        int qx = t & 7;
        int ry = t >> 3;

        int goff[5], soff[5]; bool gval[5];
        #pragma unroll
        for (int s = 0; s < 5; s++) {
            int i = t + s * 256;
            bool inr = (i < 34 * 34);
            int hy = inr ? (i / 34) : 0;
            int hx = inr ? (i - hy * 34) : 0;
            int gy = ty0 + hy - 1, gx = tx0 + hx - 1;
            gval[s] = inr && ((unsigned)gy < 64u) && ((unsigned)gx < 64u);
            goff[s] = gy * 64 + gx;
            soff[s] = inr ? (hy * 35 + hx) : -1;
        }
        int ci0 = split * 32;
        const float* base = (ci0 < 256 ? res : S) + ((size_t)b * 256 + (ci0 & 255)) * HW;
        bool wv_t = t < 54;
        int j = t / 9, k = t - j * 9;
        const float* wbase = wv_t ? ((j < 4) ? &ow[((size_t)j * CIN + ci0) * 9 + k]
                                             : &aw[((size_t)(j - 4) * CIN + ci0) * 9 + k])
                                  : ow;
        float acc[6][4];
        #pragma unroll
        for (int jj = 0; jj < 6; jj++)
            #pragma unroll
            for (int q = 0; q < 4; q++) acc[jj][q] = 0.f;

        float v[5]; float wv = 0.f;
        #pragma unroll
        for (int s = 0; s < 5; s++) v[s] = gval[s] ? base[goff[s]] : 0.f;
        if (wv_t) wv = wbase[0];

        for (int cc = 0; cc < 32; cc++) {
            #pragma unroll
            for (int s = 0; s < 5; s++)
                if (soff[s] >= 0) u.cv.sh[soff[s]] = v[s];
            if (wv_t) u.cv.wsm[t] = wv;
            __syncthreads();
            if (cc < 31) {
                const float* src = base + (size_t)(cc + 1) * HW;
                #pragma unroll
                for (int s = 0; s < 5; s++) v[s] = gval[s] ? src[goff[s]] : 0.f;
                if (wv_t) wv = wbase[(size_t)(cc + 1) * 9];
            }
            float pix[3][6];
            #pragma unroll
            for (int dy = 0; dy < 3; dy++)
                #pragma unroll
                for (int dx = 0; dx < 6; dx++)
                    pix[dy][dx] = u.cv.sh[(ry + dy) * 35 + qx * 4 + dx];
            #pragma unroll
            for (int jj = 0; jj < 6; jj++)
                #pragma unroll
                for (int ky = 0; ky < 3; ky++)
                    #pragma unroll
                    for (int kx = 0; kx < 3; kx++) {
                        float w = u.cv.wsm[jj * 9 + ky * 3 + kx];
                        #pragma unroll
                        for (int q = 0; q < 4; q++)
                            acc[jj][q] += w * pix[ky][kx + q];
                    }
            __syncthreads();
        }
        float* dst = g_off_partial + ((size_t)split * B + b) * 6 * HW;
        #pragma unroll
        for (int jj = 0; jj < 6; jj++)
            #pragma unroll
            for (int q = 0; q < 4; q++) {
                int gy = ty0 + ry, gx = tx0 + qx * 4 + q;
                dst[(size_t)jj * HW + gy * 64 + gx] = acc[jj][q];
            }
    } else {
        // ---------------- alpha ----------------
        int b = blk - 1024;
        float s = 0.f;
        for (int k = t; k < TEMB; k += 256) {
            float x = temb[b * TEMB + k];
            s += (x / (1.f + expf(-x))) * tw[k];
        }
        u.red[t] = s; __syncthreads();
        for (int o = 128; o > 0; o >>= 1) {
            if (t < o) u.red[t] += u.red[t + o];
            __syncthreads();
        }
        if (t == 0) g_alpha[b] = 1.f / (1.f + expf(-(u.red[0] + tb[0])));
    }
}

// ---------------- combine splits, bias, sigmoid, |off| partials ----------------
__global__ void __launch_bounds__(256) finalize_kernel(
        const float* __restrict__ ob, const float* __restrict__ ab) {
    int bc = blockIdx.x;
    int chunk = blockIdx.y;
    int b = bc / 6, ch = bc - b * 6;
    float bias = (ch < 4) ? ob[ch] : ab[ch - 4];
    int t = threadIdx.x;
    float lsum = 0.f;
    for (int px = chunk * 512 + t; px < (chunk + 1) * 512; px += 256) {
        float v = bias;
        #pragma unroll
        for (int s = 0; s < NSPLIT; s++)
            v += g_off_partial[(((size_t)s * B + b) * 6 + ch) * HW + px];
        if (ch < 4) {
            g_off[(size_t)(b * 4 + ch) * HW + px] = v;
            lsum += fabsf(v);
        } else {
            g_attn[(size_t)(b * 2 + (ch - 4)) * HW + px] = 1.f / (1.f + expf(-v));
        }
    }
    if (ch < 4) {
        __shared__ float red[256];
        red[t] = lsum; __syncthreads();
        for (int o = 128; o > 0; o >>= 1) {
            if (t < o) red[t] += red[t + o];
            __syncthreads();
        }
        if (t == 0) g_loss_partial[(b * 4 + ch) * 8 + chunk] = red[0];
    }
}

// ---------------- bilinear sampling + (last block) loss reduction ----------------
__global__ void __launch_bounds__(256) sample_kernel(
        const float* __restrict__ Wp, const float* __restrict__ bpts,
        float* __restrict__ out, int loss_idx) {
    if (blockIdx.x == 8192) {
        int t = threadIdx.x;
        __shared__ float red[256];
        red[t] = g_loss_partial[t];
        __syncthreads();
        for (int o = 128; o > 0; o >>= 1) {
            if (t < o) red[t] += red[t + o];
            __syncthreads();
        }
        if (t == 0) out[loss_idx] = red[0] * (1.f / 131072.f);
        return;
    }
    int widx = blockIdx.x * 8 + (threadIdx.x >> 5);
    int lane = threadIdx.x & 31;
    int b    = widx >> 13;
    int head = (widx >> 12) & 1;
    int px   = widx & 4095;
    int py   = px >> 6;
    int pxx  = px & 63;

    float off0 = g_off[(size_t)((b * 2 + head) * 2 + 0) * HW + px];
    float off1 = g_off[(size_t)((b * 2 + head) * 2 + 1) * HW + px];
    float a    = g_attn[(size_t)(b * 2 + head) * HW + px];

    float ybase = (float)py  * (2.0f / 63.0f) - 1.0f;
    float xbase = (float)pxx * (2.0f / 63.0f) - 1.0f;

    const __nv_bfloat16* spb = g_sp + (size_t)b * HW * C;
    int c8 = lane * 8;
    float acc[8];
    #pragma unroll
    for (int i = 0; i < 8; i++) acc[i] = 0.f;

    #pragma unroll
    for (int p = 0; p < POINTS; p++) {
        float g0 = ybase + __ldg(&bpts[p * 2 + 0]) + off0;
        float g1 = xbase + __ldg(&bpts[p * 2 + 1]) + off1;
        float gx = (g0 + 1.f) * 0.5f * 63.f;
        float gy = (g1 + 1.f) * 0.5f * 63.f;
        float x0f = floorf(gx), y0f = floorf(gy);
        float fx = gx - x0f, fy = gy - y0f;
        float scale = __ldg(&Wp[head * POINTS + p]) * a;
        float w00 = (1.f - fx) * (1.f - fy) * scale;
        float w10 = fx * (1.f - fy) * scale;
        float w01 = (1.f - fx) * fy * scale;
        float w11 = fx * fy * scale;
        bool vx0 = (x0f >= 0.f)  && (x0f <= 63.f);
        bool vx1 = (x0f >= -1.f) && (x0f <= 62.f);
        bool vy0 = (y0f >= 0.f)  && (y0f <= 63.f);
        bool vy1 = (y0f >= -1.f) && (y0f <= 62.f);
        int xi0 = (int)x0f, yi0 = (int)y0f;

        #pragma unroll
        for (int corner = 0; corner < 4; corner++) {
            int cy = corner >> 1, cx = corner & 1;
            bool ok = (cx ? vx1 : vx0) && (cy ? vy1 : vy0);
            float w = cx ? (cy ? w11 : w10) : (cy ? w01 : w00);
            if (ok) {
                uint4 uu = *(const uint4*)&spb[(size_t)((yi0 + cy) * 64 + xi0 + cx) * C + c8];
                const __nv_bfloat162* h = (const __nv_bfloat162*)&uu;
                #pragma unroll
                for (int i = 0; i < 4; i++) {
                    float2 f = __bfloat1622float2(h[i]);
                    acc[i * 2]     += w * f.x;
                    acc[i * 2 + 1] += w * f.y;
                }
            }
        }
    }
    __nv_bfloat16* dst = g_hv + ((size_t)(b * HW + px) * 512 + head * 256 + c8);
    uint4 o;
    __nv_bfloat162* oh = (__nv_bfloat162*)&o;
    #pragma unroll
    for (int i = 0; i < 4; i++)
        oh[i] = __floats2bfloat162_rn(acc[i * 2], acc[i * 2 + 1]);
    *(uint4*)dst = o;
}

// ---------------- fuse 1x1 GEMM (bf16) + gate epilogue ----------------
#define KP 40
__global__ void __launch_bounds__(256) fuse_gemm_bf16(
        const float* __restrict__ Fw, const float* __restrict__ fb,
        const float* __restrict__ res, float* __restrict__ out) {
    int b  = blockIdx.z;
    int m0 = blockIdx.x * 128;
    int n0 = blockIdx.y * 128;
    __shared__ __align__(16) __nv_bfloat16 As[128 * KP];
    __shared__ __align__(16) __nv_bfloat16 Bs[128 * KP];
    int t = threadIdx.x, lane = t & 31, warp = t >> 5;
    int wm = warp >> 1, wn = warp & 1;
    int g = lane >> 2, tg = lane & 3;

    float acc[2][8][4];
    #pragma unroll
    for (int mt = 0; mt < 2; mt++)
        #pragma unroll
        for (int nt = 0; nt < 8; nt++)
            #pragma unroll
            for (int i = 0; i < 4; i++) acc[mt][nt][i] = 0.f;

    const __nv_bfloat16* Ab = g_hv + (size_t)b * HW * 512;
    int arn[2], ark[2], brn[4], brk[4];
    #pragma unroll
    for (int i = 0; i < 2; i++) { int id = t + i * 256; arn[i] = id >> 2; ark[i] = id & 3; }
    #pragma unroll
    for (int i = 0; i < 4; i++) { int id = t + i * 256; brn[i] = id >> 3; brk[i] = id & 7; }

    uint4 pa[2]; float4 pb[4];
    #pragma unroll
    for (int i = 0; i < 2; i++)
        pa[i] = *(const uint4*)&Ab[(size_t)(m0 + arn[i]) * 512 + ark[i] * 8];
    #pragma unroll
    for (int i = 0; i < 4; i++)
        pb[i] = *(const float4*)&Fw[(size_t)(n0 + brn[i]) * 512 + brk[i] * 4];

    #pragma unroll
    for (int i = 0; i < 2; i++) {
        *(uint2*)&As[arn[i] * KP + ark[i] * 8]     = make_uint2(pa[i].x, pa[i].y);
        *(uint2*)&As[arn[i] * KP + ark[i] * 8 + 4] = make_uint2(pa[i].z, pa[i].w);
    }
    #pragma unroll
    for (int i = 0; i < 4; i++)
        *(uint2*)&Bs[brn[i] * KP + brk[i] * 4] =
            make_uint2(packbf(pb[i].x, pb[i].y), packbf(pb[i].z, pb[i].w));
    __syncthreads();

    for (int s = 0; s < 16; s++) {
        if (s < 15) {
            int k0 = (s + 1) * 32;
            #pragma unroll
            for (int i = 0; i < 2; i++)
                pa[i] = *(const uint4*)&Ab[(size_t)(m0 + arn[i]) * 512 + k0 + ark[i] * 8];
            #pragma unroll
            for (int i = 0; i < 4; i++)
                pb[i] = *(const float4*)&Fw[(size_t)(n0 + brn[i]) * 512 + k0 + brk[i] * 4];
        }
        #pragma unroll
        for (int kk = 0; kk < 2; kk++) {
            uint32_t a[2][4];
            #pragma unroll
            for (int mt = 0; mt < 2; mt++) {
                int cm = (wm * 32 + mt * 16 + g) * KP + kk * 16 + tg * 2;
                a[mt][0] = *(uint32_t*)&As[cm];
                a[mt][1] = *(uint32_t*)&As[cm + 8 * KP];
                a[mt][2] = *(uint32_t*)&As[cm + 8];
                a[mt][3] = *(uint32_t*)&As[cm + 8 * KP + 8];
            }
            #pragma unroll
            for (int nt = 0; nt < 8; nt++) {
                int cn = (wn * 64 + nt * 8 + g) * KP + kk * 16 + tg * 2;
                uint32_t b0 = *(uint32_t*)&Bs[cn];
                uint32_t b1 = *(uint32_t*)&Bs[cn + 8];
                #pragma unroll
                for (int mt = 0; mt < 2; mt++)
                    mma_bf16(acc[mt][nt], a[mt][0], a[mt][1], a[mt][2], a[mt][3], b0, b1);
            }
        }
        if (s < 15) {
            __syncthreads();
            #pragma unroll
            for (int i = 0; i < 2; i++) {
                *(uint2*)&As[arn[i] * KP + ark[i] * 8]     = make_uint2(pa[i].x, pa[i].y);
                *(uint2*)&As[arn[i] * KP + ark[i] * 8 + 4] = make_uint2(pa[i].z, pa[i].w);
            }
            #pragma unroll
            for (int i = 0; i < 4; i++)
                *(uint2*)&Bs[brn[i] * KP + brk[i] * 4] =
                    make_uint2(packbf(pb[i].x, pb[i].y), packbf(pb[i].z, pb[i].w));
            __syncthreads();
        }
    }

    float al = g_alpha[b];
    float ial = 1.f - al;
    #pragma unroll
    for (int nt = 0; nt < 8; nt++) {
        int o = n0 + wn * 64 + nt * 8 + tg * 2;
        float b0v = __ldg(&fb[o]), b1v = __ldg(&fb[o + 1]);
        #pragma unroll
        for (int mt = 0; mt < 2; mt++) {
            int px = m0 + wm * 32 + mt * 16 + g;
            size_t i00 = ((size_t)(b * C + o)) * HW + px;
            size_t i01 = ((size_t)(b * C + o + 1)) * HW + px;
            out[i00]     = al * (acc[mt][nt][0] + b0v) + ial * res[i00];
            out[i01]     = al * (acc[mt][nt][1] + b1v) + ial * res[i01];
            out[i00 + 8] = al * (acc[mt][nt][2] + b0v) + ial * res[i00 + 8];
            out[i01 + 8] = al * (acc[mt][nt][3] + b1v) + ial * res[i01 + 8];
        }
    }
}

// ---------------- launch ----------------
extern "C" void kernel_launch(void* const* d_in, const int* in_sizes, int n_in,
                              void* d_out, int out_size) {
    const float* res   = (const float*)d_in[0];
    const float* style = (const float*)d_in[1];
    const float* temb  = (const float*)d_in[2];
    const float* spw   = (const float*)d_in[3];
    const float* spb   = (const float*)d_in[4];
    const float* ow    = (const float*)d_in[5];
    const float* ob    = (const float*)d_in[6];
    const float* aw    = (const float*)d_in[7];
    const float* ab    = (const float*)d_in[8];
    const float* Wp    = (const float*)d_in[9];
    const float* fw    = (const float*)d_in[10];
    const float* fb    = (const float*)d_in[11];
    const float* tw    = (const float*)d_in[12];
    const float* tb    = (const float*)d_in[13];
    const float* bpts  = (const float*)d_in[14];
    float* out = (float*)d_out;

    front_kernel<<<1032, 256>>>(style, spw, spb, res, ow, aw, temb, tw, tb);
    finalize_kernel<<<dim3(48, 8), 256>>>(ob, ab);
    sample_kernel<<<8193, 256>>>(Wp, bpts, out, out_size - 1);
    fuse_gemm_bf16<<<dim3(32, 2, B), 256>>>(fw, fb, res, out);
}